// round 9
// baseline (speedup 1.0000x reference)
#include <cuda_runtime.h>

// Cost-volume construction:
//   out[0, c,      d, h, w] = imgl[0, c, h, w]                      (broadcast over d)
//   out[0, c + 32, d, h, w] = (w >= d) ? imgr[0, c, h, w - d] : 0
// Shapes: imgl/imgr (1, 32, 256, 480) f32, out (1, 64, 32, 256, 480) f32.
//
// R9 = R5 (159.7us best; DRAM traffic == output size, 80% of spec BW = write
// ceiling) with exactly ONE variable changed: default-policy stores instead
// of .cs streaming. A/B tests whether L2 dirty-line carryover / writeback
// batching beats explicit evict-first drain. All else identical to R5:
// thread-contiguous float4, block 512, DSPLIT 8, interleaved L/R streams.

constexpr int C  = 32;
constexpr int D  = 32;
constexpr int H2 = 256;
constexpr int W2 = 480;
constexpr int W4 = W2 / 4;              // 120 float4 per row
constexpr int PLANE = H2 * W2;          // 122880 floats
constexpr int CH    = D * PLANE;        // 3,932,160 floats per out-channel
constexpr int DSPLIT = 8;               // disparities per thread
constexpr int NSPLIT = D / DSPLIT;      // 4

__global__ __launch_bounds__(512, 4) void cost_volume_kernel(
    const float* __restrict__ imgl,
    const float* __restrict__ imgr,
    float* __restrict__ out)
{
    int idx = blockIdx.x * blockDim.x + threadIdx.x;

    int w4 = idx % W4;
    int t  = idx / W4;
    int h  = t % H2;
    t /= H2;
    int c     = t % C;
    int split = t / C;                  // 0..3
    int w  = w4 * 4;
    int d0 = split * DSPLIT;

    // ---- Left operand: one float4, broadcast over DSPLIT disparities ----
    const float4 l = *reinterpret_cast<const float4*>(imgl + c * PLANE + h * W2 + w);

    // ---- Right operand: sliding 4-float register window ----
    const float* rrow = imgr + c * PLANE + h * W2;
    int s = w - d0;
    float4 r;
    r.x = (s     >= 0) ? rrow[s]     : 0.0f;
    r.y = (s + 1 >= 0) ? rrow[s + 1] : 0.0f;
    r.z = (s + 2 >= 0) ? rrow[s + 2] : 0.0f;
    r.w = (s + 3 >= 0) ? rrow[s + 3] : 0.0f;

    float* outL = out + c * CH       + d0 * PLANE + h * W2 + w;
    float* outR = out + (c + C) * CH + d0 * PLANE + h * W2 + w;

    // interleaved stores: both write streams active every iteration
    *reinterpret_cast<float4*>(outL) = l;
    *reinterpret_cast<float4*>(outR) = r;

#pragma unroll
    for (int i = 1; i < DSPLIT; ++i) {
        // window slides left by one element per disparity step
        r.w = r.z;
        r.z = r.y;
        r.y = r.x;
        int src = s - i;
        r.x = (src >= 0) ? __ldg(rrow + src) : 0.0f;
        *reinterpret_cast<float4*>(outL + i * PLANE) = l;
        *reinterpret_cast<float4*>(outR + i * PLANE) = r;
    }
}

extern "C" void kernel_launch(void* const* d_in, const int* in_sizes, int n_in,
                              void* d_out, int out_size)
{
    const float* imgl = (const float*)d_in[0];
    const float* imgr = (const float*)d_in[1];
    float* out = (float*)d_out;

    const int total = NSPLIT * C * H2 * W4;          // 3,932,160 threads
    const int block = 512;
    const int grid  = (total + block - 1) / block;   // 7680 blocks
    cost_volume_kernel<<<grid, block>>>(imgl, imgr, out);
}

// round 10
// speedup vs baseline: 1.0903x; 1.0903x over previous
#include <cuda_runtime.h>

// Cost-volume construction:
//   out[0, c,      d, h, w] = imgl[0, c, h, w]                      (broadcast over d)
//   out[0, c + 32, d, h, w] = (w >= d) ? imgr[0, c, h, w - d] : 0
// Shapes: imgl/imgr (1, 32, 256, 480) f32, out (1, 64, 32, 256, 480) f32.
//
// R10 = R5 (159.7us best) with block 512 -> 1024: 16KB contiguous CTA
// footprint per d-plane visit (longest page-hit run without changing the
// proven per-thread layout). Session conclusions baked in:
//  - thread-contiguous float4 (R4/R8 wider layouts broke sector fill or
//    raised traffic)
//  - .cs streaming stores mandatory (R9 default policy thrashed L2 inputs,
//    +70MB traffic/replay)
//  - interleaved L/R write streams (R5 > R3)
//  - DRAM traffic == output size (1.007GB) at ~6.35TB/s = HBM write ceiling.

constexpr int C  = 32;
constexpr int D  = 32;
constexpr int H2 = 256;
constexpr int W2 = 480;
constexpr int W4 = W2 / 4;              // 120 float4 per row
constexpr int PLANE = H2 * W2;          // 122880 floats
constexpr int CH    = D * PLANE;        // 3,932,160 floats per out-channel
constexpr int DSPLIT = 8;               // disparities per thread
constexpr int NSPLIT = D / DSPLIT;      // 4
constexpr int BLOCK  = 1024;

__global__ __launch_bounds__(BLOCK, 2) void cost_volume_kernel(
    const float* __restrict__ imgl,
    const float* __restrict__ imgr,
    float* __restrict__ out)
{
    int idx = blockIdx.x * blockDim.x + threadIdx.x;

    int w4 = idx % W4;
    int t  = idx / W4;
    int h  = t % H2;
    t /= H2;
    int c     = t % C;
    int split = t / C;                  // 0..3
    int w  = w4 * 4;
    int d0 = split * DSPLIT;

    // ---- Left operand: one float4, broadcast over DSPLIT disparities ----
    const float4 l = *reinterpret_cast<const float4*>(imgl + c * PLANE + h * W2 + w);

    // ---- Right operand: sliding 4-float register window ----
    const float* rrow = imgr + c * PLANE + h * W2;
    int s = w - d0;
    float4 r;
    r.x = (s     >= 0) ? rrow[s]     : 0.0f;
    r.y = (s + 1 >= 0) ? rrow[s + 1] : 0.0f;
    r.z = (s + 2 >= 0) ? rrow[s + 2] : 0.0f;
    r.w = (s + 3 >= 0) ? rrow[s + 3] : 0.0f;

    float* outL = out + c * CH       + d0 * PLANE + h * W2 + w;
    float* outR = out + (c + C) * CH + d0 * PLANE + h * W2 + w;

    // interleaved stores: both write streams active every iteration
    __stcs(reinterpret_cast<float4*>(outL), l);
    __stcs(reinterpret_cast<float4*>(outR), r);

#pragma unroll
    for (int i = 1; i < DSPLIT; ++i) {
        // window slides left by one element per disparity step
        r.w = r.z;
        r.z = r.y;
        r.y = r.x;
        int src = s - i;
        r.x = (src >= 0) ? __ldg(rrow + src) : 0.0f;
        __stcs(reinterpret_cast<float4*>(outL + i * PLANE), l);
        __stcs(reinterpret_cast<float4*>(outR + i * PLANE), r);
    }
}

extern "C" void kernel_launch(void* const* d_in, const int* in_sizes, int n_in,
                              void* d_out, int out_size)
{
    const float* imgl = (const float*)d_in[0];
    const float* imgr = (const float*)d_in[1];
    float* out = (float*)d_out;

    const int total = NSPLIT * C * H2 * W4;          // 3,932,160 threads
    const int grid  = (total + BLOCK - 1) / BLOCK;   // 3840 blocks
    cost_volume_kernel<<<grid, BLOCK>>>(imgl, imgr, out);
}